// round 15
// baseline (speedup 1.0000x reference)
#include <cuda_runtime.h>
#include <math.h>
#include <stdint.h>

#define NATOMS 16384
#define NEDGES 262144
#define DIM    128
#define GDIM   50
#define LINT   4
#define TBL    4096
#define NMOLS  32

#define DMAXF  1.74f
#define LOG2C  0.69314718055994530942f
#define PIC    3.14159265358979323846f

// -------------------- scratch (static device globals; no runtime alloc) ----
__device__ __align__(16) float g_h[NATOMS * DIM];
__device__ __align__(16) float g_xh[NATOMS * DIM];
__device__ __align__(16) float g_agg[NATOMS * DIM];
__device__ __align__(16) float g_dist[NEDGES];
__device__ __align__(16) float g_table[(size_t)LINT * TBL * DIM];
__device__ __align__(16) float g_u[DIM];
__device__ __align__(16) float g_v[DIM];

__device__ __forceinline__ float sspf(float x) {
    return fmaxf(x, 0.0f) + log1pf(expf(-fabsf(x))) - LOG2C;
}

// -------------------- prep: u = emb_W@cf1[0], v = emb_b@cf1[0] -------------
__global__ void k_prep(const float* __restrict__ eW, const float* __restrict__ eb,
                       const float* __restrict__ cf1) {
    int f = threadIdx.x;
    float u = 0.f, v = 0.f;
    #pragma unroll 8
    for (int d = 0; d < DIM; ++d) {
        float w = __ldg(cf1 + d * DIM + f);
        u = fmaf(__ldg(eW + d), w, u);
        v = fmaf(__ldg(eb + d), w, v);
    }
    g_u[f] = u;
    g_v[f] = v;
}

// -------------------- embed: h = z*W+b; xh = z*u+v; zero agg + out ---------
__global__ void k_embed(const float* __restrict__ z,
                        const float* __restrict__ eW,
                        const float* __restrict__ eb,
                        float* __restrict__ out) {
    int idx = blockIdx.x * blockDim.x + threadIdx.x;   // float4 index
    if (blockIdx.x == 0 && threadIdx.x < NMOLS) out[threadIdx.x] = 0.0f;
    int n = idx >> 5;
    int c = (idx & 31) << 2;
    float zv = __ldg(z + n);
    float4 w = *reinterpret_cast<const float4*>(eW + c);
    float4 b = *reinterpret_cast<const float4*>(eb + c);
    float4 h;
    h.x = fmaf(zv, w.x, b.x); h.y = fmaf(zv, w.y, b.y);
    h.z = fmaf(zv, w.z, b.z); h.w = fmaf(zv, w.w, b.w);
    size_t off = (size_t)n * DIM + c;
    *reinterpret_cast<float4*>(g_h + off) = h;
    float4 u = *reinterpret_cast<const float4*>(g_u + c);
    float4 v = *reinterpret_cast<const float4*>(g_v + c);
    float4 x;
    x.x = fmaf(zv, u.x, v.x); x.y = fmaf(zv, u.y, v.y);
    x.z = fmaf(zv, u.z, v.z); x.w = fmaf(zv, u.w, v.w);
    *reinterpret_cast<float4*>(g_xh + off) = x;
    *reinterpret_cast<float4*>(g_agg + off) = make_float4(0.f, 0.f, 0.f, 0.f);
}

// -------------------- edge distances ---------------------------------------
__global__ void k_dist(const float* __restrict__ pos,
                       const int* __restrict__ src,
                       const int* __restrict__ dst) {
    int e = blockIdx.x * blockDim.x + threadIdx.x;
    int s = __ldg(src + e);
    int d = __ldg(dst + e);
    float dx = __ldg(pos + s * 3 + 0) - __ldg(pos + d * 3 + 0);
    float dy = __ldg(pos + s * 3 + 1) - __ldg(pos + d * 3 + 1);
    float dz = __ldg(pos + s * 3 + 2) - __ldg(pos + d * 3 + 2);
    g_dist[e] = sqrtf(fmaf(dx, dx, fmaf(dy, dy, fmaf(dz, dz, 1e-12f))));
}

// -------------------- table build as two chained GEMMs ---------------------
// out[l,t,f] = (ssp(rbf[t,:]@W1[l] + b1[l]) @ W2[l] + b2[l]) * C(t)
// grid = LINT * (TBL/128) = 128 blocks, 256 threads, 8x8 register tiles.
__global__ void __launch_bounds__(256, 1) k_table(
    const float* __restrict__ W1, const float* __restrict__ b1,
    const float* __restrict__ W2, const float* __restrict__ b2) {
    extern __shared__ float sm[];
    float* sX = sm;                  // 128*132  (x1 after GEMM1)
    float* sW = sm + 128 * 132;      // 128*128  (W1 first 50 rows, then W2)
    float* sR = sW + DIM * DIM;      // 128*52   (rbf tile)
    int tid = threadIdx.x;
    int l   = blockIdx.x >> 5;
    int t0  = (blockIdx.x & 31) * 128;
    const float dstep = DMAXF / (float)(TBL - 1);

    // stage W1 [50][128]
    for (int i = tid; i < GDIM * DIM; i += 256)
        sW[i] = W1[(size_t)l * GDIM * DIM + i];
    // rbf tile [128][50] (stride 52)
    for (int idx = tid; idx < 128 * GDIM; idx += 256) {
        int m = idx / GDIM, g = idx - m * GDIM;
        float d = (float)(t0 + m) * dstep;
        float u = d - (float)g * (5.0f / 49.0f);
        sR[m * 52 + g] = expf(-4.0f * u * u);
    }
    __syncthreads();

    int m0 = (tid >> 4) * 8, n0 = (tid & 15) * 8;
    float c[8][8];
    #pragma unroll
    for (int i = 0; i < 8; ++i)
        #pragma unroll
        for (int j = 0; j < 8; ++j) c[i][j] = 0.f;

    // GEMM1: [128x50] @ [50x128]
    #pragma unroll 2
    for (int k = 0; k < GDIM; ++k) {
        float4 b0 = *reinterpret_cast<const float4*>(sW + k * DIM + n0);
        float4 b1v = *reinterpret_cast<const float4*>(sW + k * DIM + n0 + 4);
        float bb[8] = {b0.x, b0.y, b0.z, b0.w, b1v.x, b1v.y, b1v.z, b1v.w};
        #pragma unroll
        for (int i = 0; i < 8; ++i) {
            float a = sR[(m0 + i) * 52 + k];
            #pragma unroll
            for (int j = 0; j < 8; ++j) c[i][j] = fmaf(a, bb[j], c[i][j]);
        }
    }
    __syncthreads();   // done reading sW(W1); sR no longer needed

    // x1 = ssp(c + b1) -> sX; stage W2
    {
        float bb[8];
        #pragma unroll
        for (int j = 0; j < 8; ++j) bb[j] = __ldg(b1 + l * DIM + n0 + j);
        #pragma unroll
        for (int i = 0; i < 8; ++i)
            #pragma unroll
            for (int j = 0; j < 8; ++j)
                sX[(m0 + i) * 132 + n0 + j] = sspf(c[i][j] + bb[j]);
    }
    for (int idx = tid; idx < DIM * DIM / 4; idx += 256)
        *reinterpret_cast<float4*>(sW + idx * 4) =
            *reinterpret_cast<const float4*>(W2 + (size_t)l * DIM * DIM + idx * 4);
    __syncthreads();

    #pragma unroll
    for (int i = 0; i < 8; ++i)
        #pragma unroll
        for (int j = 0; j < 8; ++j) c[i][j] = 0.f;
    // GEMM2: [128x128] @ [128x128]
    #pragma unroll 2
    for (int k = 0; k < DIM; ++k) {
        float4 b0 = *reinterpret_cast<const float4*>(sW + k * DIM + n0);
        float4 b1v = *reinterpret_cast<const float4*>(sW + k * DIM + n0 + 4);
        float bb[8] = {b0.x, b0.y, b0.z, b0.w, b1v.x, b1v.y, b1v.z, b1v.w};
        #pragma unroll
        for (int i = 0; i < 8; ++i) {
            float a = sX[(m0 + i) * 132 + k];
            #pragma unroll
            for (int j = 0; j < 8; ++j) c[i][j] = fmaf(a, bb[j], c[i][j]);
        }
    }

    // store: (c + b2) * C(d)
    {
        float bb[8];
        #pragma unroll
        for (int j = 0; j < 8; ++j) bb[j] = __ldg(b2 + l * DIM + n0 + j);
        #pragma unroll
        for (int i = 0; i < 8; ++i) {
            int row = m0 + i;
            float d = (float)(t0 + row) * dstep;
            float C = 0.5f * (cosf(d * (PIC / 5.0f)) + 1.0f);
            size_t off = ((size_t)l * TBL + t0 + row) * DIM + n0;
            *reinterpret_cast<float4*>(g_table + off) = make_float4(
                (c[i][0] + bb[0]) * C, (c[i][1] + bb[1]) * C,
                (c[i][2] + bb[2]) * C, (c[i][3] + bb[3]) * C);
            *reinterpret_cast<float4*>(g_table + off + 4) = make_float4(
                (c[i][4] + bb[4]) * C, (c[i][5] + bb[5]) * C,
                (c[i][6] + bb[6]) * C, (c[i][7] + bb[7]) * C);
        }
    }
}

// -------------------- edge pass: gather * lerp(table) -> scatter-add -------
__global__ void k_edge(const int* __restrict__ src, const int* __restrict__ dst, int l) {
    int gt   = blockIdx.x * 256 + threadIdx.x;
    int e    = gt >> 5;
    int lane = gt & 31;
    int s  = __ldg(src + e);
    int dd = __ldg(dst + e);
    float dist = g_dist[e];
    float p = dist * ((float)(TBL - 1) / DMAXF);
    int   i = (int)p;
    i = min(i, TBL - 2);
    float w = p - (float)i;
    const float4* trow = reinterpret_cast<const float4*>(g_table + ((size_t)l * TBL + i) * DIM) + lane;
    float4 a = trow[0];
    float4 b = trow[32];
    float4 xj = reinterpret_cast<const float4*>(g_xh + (size_t)s * DIM)[lane];
    float4 v;
    v.x = xj.x * fmaf(w, b.x - a.x, a.x);
    v.y = xj.y * fmaf(w, b.y - a.y, a.y);
    v.z = xj.z * fmaf(w, b.z - a.z, a.z);
    v.w = xj.w * fmaf(w, b.w - a.w, a.w);
    float* outp = g_agg + (size_t)dd * DIM + lane * 4;
    asm volatile("red.global.add.v4.f32 [%0], {%1,%2,%3,%4};"
                 :: "l"(outp), "f"(v.x), "f"(v.y), "f"(v.z), "f"(v.w) : "memory");
}

// -------------------- shared-memory 128x128x128 GEMM micro-kernel ----------
// sA: [128][132] row-major A tile, sW: [128][128] row-major weights (k,n)
__device__ __forceinline__ void mma128(const float* __restrict__ sA,
                                       const float* __restrict__ sW,
                                       float c[8][8], int m0, int n0) {
    #pragma unroll 2
    for (int k = 0; k < DIM; ++k) {
        float4 b0 = *reinterpret_cast<const float4*>(sW + k * DIM + n0);
        float4 b1 = *reinterpret_cast<const float4*>(sW + k * DIM + n0 + 4);
        float bb[8] = {b0.x, b0.y, b0.z, b0.w, b1.x, b1.y, b1.z, b1.w};
        #pragma unroll
        for (int i = 0; i < 8; ++i) {
            float a = sA[(m0 + i) * 132 + k];
            #pragma unroll
            for (int j = 0; j < 8; ++j) c[i][j] = fmaf(a, bb[j], c[i][j]);
        }
    }
}

// -------------------- fused node update: 3 chained GEMMs per tile ----------
// x1 = ssp(agg@cf2 + b); x2 = x1@int + b; h += x2; xh = h@cf1_next (if any).
// Also zeroes its g_agg tile for the next layer's scatter.
__global__ void __launch_bounds__(256, 1) k_node(
    const float* __restrict__ cf2W, const float* __restrict__ cf2b,
    const float* __restrict__ intW, const float* __restrict__ intb,
    const float* __restrict__ cf1Wn, int hasNext) {
    extern __shared__ float sm[];
    float* sA = sm;                 // 128*132
    float* sW = sm + 128 * 132;     // 128*128
    int tid  = threadIdx.x;
    int row0 = blockIdx.x * 128;
    int m0 = (tid >> 4) * 8, n0 = (tid & 15) * 8;

    // stage A inputs: A = agg tile, W = cf2
    #pragma unroll
    for (int it = 0; it < 16; ++it) {
        int idx = tid + it * 256;          // float4 index 0..4095
        int m = idx >> 5, c4 = (idx & 31) * 4;
        *reinterpret_cast<float4*>(sA + m * 132 + c4) =
            *reinterpret_cast<const float4*>(g_agg + (size_t)(row0 + m) * DIM + c4);
        *reinterpret_cast<float4*>(sW + idx * 4) =
            *reinterpret_cast<const float4*>(cf2W + (size_t)idx * 4);
    }
    __syncthreads();
    // zero our agg tile for the next layer (overlaps with MMA below)
    if (hasNext) {
        #pragma unroll
        for (int it = 0; it < 16; ++it) {
            int idx = tid + it * 256;
            int m = idx >> 5, c4 = (idx & 31) * 4;
            *reinterpret_cast<float4*>(g_agg + (size_t)(row0 + m) * DIM + c4) =
                make_float4(0.f, 0.f, 0.f, 0.f);
        }
    }
    float c[8][8];
    #pragma unroll
    for (int i = 0; i < 8; ++i)
        #pragma unroll
        for (int j = 0; j < 8; ++j) c[i][j] = 0.f;
    mma128(sA, sW, c, m0, n0);
    __syncthreads();   // everyone done reading sA before overwrite

    // x1 = ssp(c + cf2b) into sA; load int weights
    {
        float bb[8];
        #pragma unroll
        for (int j = 0; j < 8; ++j) bb[j] = __ldg(cf2b + n0 + j);
        #pragma unroll
        for (int i = 0; i < 8; ++i)
            #pragma unroll
            for (int j = 0; j < 8; ++j)
                sA[(m0 + i) * 132 + n0 + j] = sspf(c[i][j] + bb[j]);
    }
    #pragma unroll
    for (int it = 0; it < 16; ++it) {
        int idx = tid + it * 256;
        *reinterpret_cast<float4*>(sW + idx * 4) =
            *reinterpret_cast<const float4*>(intW + (size_t)idx * 4);
    }
    __syncthreads();
    #pragma unroll
    for (int i = 0; i < 8; ++i)
        #pragma unroll
        for (int j = 0; j < 8; ++j) c[i][j] = 0.f;
    mma128(sA, sW, c, m0, n0);
    __syncthreads();

    // hnew = h + c + intb -> global (+ stage into sA if next GEMM)
    {
        float bb[8];
        #pragma unroll
        for (int j = 0; j < 8; ++j) bb[j] = __ldg(intb + n0 + j);
        #pragma unroll
        for (int i = 0; i < 8; ++i) {
            size_t off = (size_t)(row0 + m0 + i) * DIM + n0;
            float4 h0 = *reinterpret_cast<const float4*>(g_h + off);
            float4 h1 = *reinterpret_cast<const float4*>(g_h + off + 4);
            h0.x += c[i][0] + bb[0];
            h0.y += c[i][1] + bb[1];
            h0.z += c[i][2] + bb[2];
            h0.w += c[i][3] + bb[3];
            h1.x += c[i][4] + bb[4];
            h1.y += c[i][5] + bb[5];
            h1.z += c[i][6] + bb[6];
            h1.w += c[i][7] + bb[7];
            *reinterpret_cast<float4*>(g_h + off)     = h0;
            *reinterpret_cast<float4*>(g_h + off + 4) = h1;
            if (hasNext) {
                float* p = sA + (m0 + i) * 132 + n0;
                *reinterpret_cast<float4*>(p)     = h0;
                *reinterpret_cast<float4*>(p + 4) = h1;
            }
        }
    }
    if (!hasNext) return;

    #pragma unroll
    for (int it = 0; it < 16; ++it) {
        int idx = tid + it * 256;
        *reinterpret_cast<float4*>(sW + idx * 4) =
            *reinterpret_cast<const float4*>(cf1Wn + (size_t)idx * 4);
    }
    __syncthreads();
    #pragma unroll
    for (int i = 0; i < 8; ++i)
        #pragma unroll
        for (int j = 0; j < 8; ++j) c[i][j] = 0.f;
    mma128(sA, sW, c, m0, n0);
    #pragma unroll
    for (int i = 0; i < 8; ++i) {
        size_t off = (size_t)(row0 + m0 + i) * DIM + n0;
        *reinterpret_cast<float4*>(g_xh + off)     = make_float4(c[i][0], c[i][1], c[i][2], c[i][3]);
        *reinterpret_cast<float4*>(g_xh + off + 4) = make_float4(c[i][4], c[i][5], c[i][6], c[i][7]);
    }
}

// -------------------- readout: ssp(h@lin1+b)@lin2+b, segment-sum by batch --
__global__ void k_readout(const int* __restrict__ batch,
                          const float* __restrict__ l1W, const float* __restrict__ l1b,
                          const float* __restrict__ l2W, const float* __restrict__ l2b,
                          float* __restrict__ out) {
    __shared__ float sW1[DIM * 64];
    __shared__ float sW2[64];
    __shared__ float sh[8 * DIM];
    int tid = threadIdx.x, lane = tid & 31, wid = tid >> 5;
    for (int i = tid; i < DIM * 64; i += 256) sW1[i] = l1W[i];
    if (tid < 64) sW2[tid] = l2W[tid];
    int n = blockIdx.x * 8 + wid;
    float4 hv = reinterpret_cast<const float4*>(g_h + (size_t)n * DIM)[lane];
    *reinterpret_cast<float4*>(sh + wid * DIM + lane * 4) = hv;
    __syncthreads();
    float t0 = __ldg(l1b + lane), t1 = __ldg(l1b + lane + 32);
    const float* hr = sh + wid * DIM;
    #pragma unroll 8
    for (int j = 0; j < DIM; ++j) {
        float hj = hr[j];
        t0 = fmaf(hj, sW1[j * 64 + lane], t0);
        t1 = fmaf(hj, sW1[j * 64 + lane + 32], t1);
    }
    float y = sspf(t0) * sW2[lane] + sspf(t1) * sW2[lane + 32];
    #pragma unroll
    for (int o = 16; o; o >>= 1) y += __shfl_xor_sync(0xffffffffu, y, o);
    if (lane == 0) atomicAdd(out + __ldg(batch + n), y + __ldg(l2b));
}

// -------------------- launch -----------------------------------------------
extern "C" void kernel_launch(void* const* d_in, const int* in_sizes, int n_in,
                              void* d_out, int out_size) {
    const float* z    = (const float*)d_in[0];
    const float* pos  = (const float*)d_in[1];
    const int*   batc = (const int*)  d_in[2];
    const int*   esrc = (const int*)  d_in[3];
    const int*   edst = (const int*)  d_in[4];
    const float* embW = (const float*)d_in[5];
    const float* embB = (const float*)d_in[6];
    const float* W1   = (const float*)d_in[7];
    const float* b1   = (const float*)d_in[8];
    const float* W2   = (const float*)d_in[9];
    const float* b2   = (const float*)d_in[10];
    const float* cf1  = (const float*)d_in[11];
    const float* cf2  = (const float*)d_in[12];
    const float* cf2b = (const float*)d_in[13];
    const float* ilW  = (const float*)d_in[14];
    const float* ilb  = (const float*)d_in[15];
    const float* l1W  = (const float*)d_in[16];
    const float* l1b  = (const float*)d_in[17];
    const float* l2W  = (const float*)d_in[18];
    const float* l2b  = (const float*)d_in[19];
    float* out = (float*)d_out;

    int smemNode = (128 * 132 + 128 * 128) * 4;              // 133120 B
    int smemTbl  = (128 * 132 + 128 * 128 + 128 * 52) * 4;   // 159744 B
    cudaFuncSetAttribute(k_node,  cudaFuncAttributeMaxDynamicSharedMemorySize, smemNode);
    cudaFuncSetAttribute(k_table, cudaFuncAttributeMaxDynamicSharedMemorySize, smemTbl);

    k_prep<<<1, DIM>>>(embW, embB, cf1);
    k_embed<<<(NATOMS * DIM / 4) / 256, 256>>>(z, embW, embB, out);
    k_dist<<<NEDGES / 256, 256>>>(pos, esrc, edst);
    k_table<<<LINT * (TBL / 128), 256, smemTbl>>>(W1, b1, W2, b2);

    for (int l = 0; l < LINT; ++l) {
        k_edge<<<NEDGES / 8, 256>>>(esrc, edst, l);
        const float* cf1n = (l + 1 < LINT) ? (cf1 + (size_t)(l + 1) * DIM * DIM) : cf1;
        k_node<<<NATOMS / 128, 256, smemNode>>>(
            cf2 + (size_t)l * DIM * DIM, cf2b + l * DIM,
            ilW + (size_t)l * DIM * DIM, ilb + l * DIM,
            cf1n, (l + 1 < LINT) ? 1 : 0);
    }
    k_readout<<<NATOMS / 8, 256>>>(batc, l1W, l1b, l2W, l2b, out);
}

// round 16
// speedup vs baseline: 1.0034x; 1.0034x over previous
#include <cuda_runtime.h>
#include <math.h>
#include <stdint.h>

#define NATOMS 16384
#define NEDGES 262144
#define DIM    128
#define GDIM   50
#define LINT   4
#define TBL    4096
#define NMOLS  32

#define DMAXF  1.74f
#define LOG2C  0.69314718055994530942f
#define PIC    3.14159265358979323846f

// -------------------- scratch (static device globals; no runtime alloc) ----
__device__ __align__(16) float g_h[NATOMS * DIM];
__device__ __align__(16) float g_xh[NATOMS * DIM];
__device__ __align__(16) float g_agg[NATOMS * DIM];
__device__ __align__(16) float g_dist[NEDGES];
__device__ __align__(16) float g_table[(size_t)LINT * TBL * DIM];
__device__ __align__(16) float g_u[DIM];
__device__ __align__(16) float g_v[DIM];

__device__ __forceinline__ float sspf(float x) {
    return fmaxf(x, 0.0f) + log1pf(expf(-fabsf(x))) - LOG2C;
}

// -------------------- prep: u = emb_W@cf1[0], v = emb_b@cf1[0] -------------
__global__ void k_prep(const float* __restrict__ eW, const float* __restrict__ eb,
                       const float* __restrict__ cf1) {
    int f = threadIdx.x;
    float u = 0.f, v = 0.f;
    #pragma unroll 8
    for (int d = 0; d < DIM; ++d) {
        float w = __ldg(cf1 + d * DIM + f);
        u = fmaf(__ldg(eW + d), w, u);
        v = fmaf(__ldg(eb + d), w, v);
    }
    g_u[f] = u;
    g_v[f] = v;
}

// -------------------- embed: h = z*W+b; xh = z*u+v; zero agg + out ---------
__global__ void k_embed(const float* __restrict__ z,
                        const float* __restrict__ eW,
                        const float* __restrict__ eb,
                        float* __restrict__ out) {
    int idx = blockIdx.x * blockDim.x + threadIdx.x;   // float4 index
    if (blockIdx.x == 0 && threadIdx.x < NMOLS) out[threadIdx.x] = 0.0f;
    int n = idx >> 5;
    int c = (idx & 31) << 2;
    float zv = __ldg(z + n);
    float4 w = *reinterpret_cast<const float4*>(eW + c);
    float4 b = *reinterpret_cast<const float4*>(eb + c);
    float4 h;
    h.x = fmaf(zv, w.x, b.x); h.y = fmaf(zv, w.y, b.y);
    h.z = fmaf(zv, w.z, b.z); h.w = fmaf(zv, w.w, b.w);
    size_t off = (size_t)n * DIM + c;
    *reinterpret_cast<float4*>(g_h + off) = h;
    float4 u = *reinterpret_cast<const float4*>(g_u + c);
    float4 v = *reinterpret_cast<const float4*>(g_v + c);
    float4 x;
    x.x = fmaf(zv, u.x, v.x); x.y = fmaf(zv, u.y, v.y);
    x.z = fmaf(zv, u.z, v.z); x.w = fmaf(zv, u.w, v.w);
    *reinterpret_cast<float4*>(g_xh + off) = x;
    *reinterpret_cast<float4*>(g_agg + off) = make_float4(0.f, 0.f, 0.f, 0.f);
}

// -------------------- edge distances ---------------------------------------
__global__ void k_dist(const float* __restrict__ pos,
                       const int* __restrict__ src,
                       const int* __restrict__ dst) {
    int e = blockIdx.x * blockDim.x + threadIdx.x;
    int s = __ldg(src + e);
    int d = __ldg(dst + e);
    float dx = __ldg(pos + s * 3 + 0) - __ldg(pos + d * 3 + 0);
    float dy = __ldg(pos + s * 3 + 1) - __ldg(pos + d * 3 + 1);
    float dz = __ldg(pos + s * 3 + 2) - __ldg(pos + d * 3 + 2);
    g_dist[e] = sqrtf(fmaf(dx, dx, fmaf(dy, dy, fmaf(dz, dz, 1e-12f))));
}

// -------------------- table build as two chained GEMMs ---------------------
// out[l,t,f] = (ssp(rbf[t,:]@W1[l] + b1[l]) @ W2[l] + b2[l]) * C(t)
// grid = LINT * (TBL/128) = 128 blocks, 256 threads, 8x8 register tiles.
__global__ void __launch_bounds__(256, 1) k_table(
    const float* __restrict__ W1, const float* __restrict__ b1,
    const float* __restrict__ W2, const float* __restrict__ b2) {
    extern __shared__ float sm[];
    float* sX = sm;                  // 128*132  (x1 after GEMM1)
    float* sW = sm + 128 * 132;      // 128*128  (W1 first 50 rows, then W2)
    float* sR = sW + DIM * DIM;      // 128*52   (rbf tile)
    int tid = threadIdx.x;
    int l   = blockIdx.x >> 5;
    int t0  = (blockIdx.x & 31) * 128;
    const float dstep = DMAXF / (float)(TBL - 1);

    // stage W1 [50][128]
    for (int i = tid; i < GDIM * DIM; i += 256)
        sW[i] = W1[(size_t)l * GDIM * DIM + i];
    // rbf tile [128][50] (stride 52)
    for (int idx = tid; idx < 128 * GDIM; idx += 256) {
        int m = idx / GDIM, g = idx - m * GDIM;
        float d = (float)(t0 + m) * dstep;
        float u = d - (float)g * (5.0f / 49.0f);
        sR[m * 52 + g] = expf(-4.0f * u * u);
    }
    __syncthreads();

    int m0 = (tid >> 4) * 8, n0 = (tid & 15) * 8;
    float c[8][8];
    #pragma unroll
    for (int i = 0; i < 8; ++i)
        #pragma unroll
        for (int j = 0; j < 8; ++j) c[i][j] = 0.f;

    // GEMM1: [128x50] @ [50x128]
    #pragma unroll 2
    for (int k = 0; k < GDIM; ++k) {
        float4 b0 = *reinterpret_cast<const float4*>(sW + k * DIM + n0);
        float4 b1v = *reinterpret_cast<const float4*>(sW + k * DIM + n0 + 4);
        float bb[8] = {b0.x, b0.y, b0.z, b0.w, b1v.x, b1v.y, b1v.z, b1v.w};
        #pragma unroll
        for (int i = 0; i < 8; ++i) {
            float a = sR[(m0 + i) * 52 + k];
            #pragma unroll
            for (int j = 0; j < 8; ++j) c[i][j] = fmaf(a, bb[j], c[i][j]);
        }
    }
    __syncthreads();   // done reading sW(W1); sR no longer needed

    // x1 = ssp(c + b1) -> sX; stage W2
    {
        float bb[8];
        #pragma unroll
        for (int j = 0; j < 8; ++j) bb[j] = __ldg(b1 + l * DIM + n0 + j);
        #pragma unroll
        for (int i = 0; i < 8; ++i)
            #pragma unroll
            for (int j = 0; j < 8; ++j)
                sX[(m0 + i) * 132 + n0 + j] = sspf(c[i][j] + bb[j]);
    }
    for (int idx = tid; idx < DIM * DIM / 4; idx += 256)
        *reinterpret_cast<float4*>(sW + idx * 4) =
            *reinterpret_cast<const float4*>(W2 + (size_t)l * DIM * DIM + idx * 4);
    __syncthreads();

    #pragma unroll
    for (int i = 0; i < 8; ++i)
        #pragma unroll
        for (int j = 0; j < 8; ++j) c[i][j] = 0.f;
    // GEMM2: [128x128] @ [128x128]
    #pragma unroll 2
    for (int k = 0; k < DIM; ++k) {
        float4 b0 = *reinterpret_cast<const float4*>(sW + k * DIM + n0);
        float4 b1v = *reinterpret_cast<const float4*>(sW + k * DIM + n0 + 4);
        float bb[8] = {b0.x, b0.y, b0.z, b0.w, b1v.x, b1v.y, b1v.z, b1v.w};
        #pragma unroll
        for (int i = 0; i < 8; ++i) {
            float a = sX[(m0 + i) * 132 + k];
            #pragma unroll
            for (int j = 0; j < 8; ++j) c[i][j] = fmaf(a, bb[j], c[i][j]);
        }
    }

    // store: (c + b2) * C(d)
    {
        float bb[8];
        #pragma unroll
        for (int j = 0; j < 8; ++j) bb[j] = __ldg(b2 + l * DIM + n0 + j);
        #pragma unroll
        for (int i = 0; i < 8; ++i) {
            int row = m0 + i;
            float d = (float)(t0 + row) * dstep;
            float C = 0.5f * (cosf(d * (PIC / 5.0f)) + 1.0f);
            size_t off = ((size_t)l * TBL + t0 + row) * DIM + n0;
            *reinterpret_cast<float4*>(g_table + off) = make_float4(
                (c[i][0] + bb[0]) * C, (c[i][1] + bb[1]) * C,
                (c[i][2] + bb[2]) * C, (c[i][3] + bb[3]) * C);
            *reinterpret_cast<float4*>(g_table + off + 4) = make_float4(
                (c[i][4] + bb[4]) * C, (c[i][5] + bb[5]) * C,
                (c[i][6] + bb[6]) * C, (c[i][7] + bb[7]) * C);
        }
    }
}

// -------------------- edge pass: gather * lerp(table) -> scatter-add -------
__global__ void k_edge(const int* __restrict__ src, const int* __restrict__ dst, int l) {
    int gt   = blockIdx.x * 256 + threadIdx.x;
    int e    = gt >> 5;
    int lane = gt & 31;
    int s  = __ldg(src + e);
    int dd = __ldg(dst + e);
    float dist = g_dist[e];
    float p = dist * ((float)(TBL - 1) / DMAXF);
    int   i = (int)p;
    i = min(i, TBL - 2);
    float w = p - (float)i;
    const float4* trow = reinterpret_cast<const float4*>(g_table + ((size_t)l * TBL + i) * DIM) + lane;
    float4 a = trow[0];
    float4 b = trow[32];
    float4 xj = reinterpret_cast<const float4*>(g_xh + (size_t)s * DIM)[lane];
    float4 v;
    v.x = xj.x * fmaf(w, b.x - a.x, a.x);
    v.y = xj.y * fmaf(w, b.y - a.y, a.y);
    v.z = xj.z * fmaf(w, b.z - a.z, a.z);
    v.w = xj.w * fmaf(w, b.w - a.w, a.w);
    float* outp = g_agg + (size_t)dd * DIM + lane * 4;
    asm volatile("red.global.add.v4.f32 [%0], {%1,%2,%3,%4};"
                 :: "l"(outp), "f"(v.x), "f"(v.y), "f"(v.z), "f"(v.w) : "memory");
}

// -------------------- shared-memory 128x128x128 GEMM micro-kernel ----------
// sA: [128][132] row-major A tile, sW: [128][128] row-major weights (k,n)
__device__ __forceinline__ void mma128(const float* __restrict__ sA,
                                       const float* __restrict__ sW,
                                       float c[8][8], int m0, int n0) {
    #pragma unroll 2
    for (int k = 0; k < DIM; ++k) {
        float4 b0 = *reinterpret_cast<const float4*>(sW + k * DIM + n0);
        float4 b1 = *reinterpret_cast<const float4*>(sW + k * DIM + n0 + 4);
        float bb[8] = {b0.x, b0.y, b0.z, b0.w, b1.x, b1.y, b1.z, b1.w};
        #pragma unroll
        for (int i = 0; i < 8; ++i) {
            float a = sA[(m0 + i) * 132 + k];
            #pragma unroll
            for (int j = 0; j < 8; ++j) c[i][j] = fmaf(a, bb[j], c[i][j]);
        }
    }
}

// -------------------- fused node update: 3 chained GEMMs per tile ----------
// x1 = ssp(agg@cf2 + b); x2 = x1@int + b; h += x2; xh = h@cf1_next (if any).
// Also zeroes its g_agg tile for the next layer's scatter.
__global__ void __launch_bounds__(256, 1) k_node(
    const float* __restrict__ cf2W, const float* __restrict__ cf2b,
    const float* __restrict__ intW, const float* __restrict__ intb,
    const float* __restrict__ cf1Wn, int hasNext) {
    extern __shared__ float sm[];
    float* sA = sm;                 // 128*132
    float* sW = sm + 128 * 132;     // 128*128
    int tid  = threadIdx.x;
    int row0 = blockIdx.x * 128;
    int m0 = (tid >> 4) * 8, n0 = (tid & 15) * 8;

    // stage A inputs: A = agg tile, W = cf2
    #pragma unroll
    for (int it = 0; it < 16; ++it) {
        int idx = tid + it * 256;          // float4 index 0..4095
        int m = idx >> 5, c4 = (idx & 31) * 4;
        *reinterpret_cast<float4*>(sA + m * 132 + c4) =
            *reinterpret_cast<const float4*>(g_agg + (size_t)(row0 + m) * DIM + c4);
        *reinterpret_cast<float4*>(sW + idx * 4) =
            *reinterpret_cast<const float4*>(cf2W + (size_t)idx * 4);
    }
    __syncthreads();
    // zero our agg tile for the next layer (overlaps with MMA below)
    if (hasNext) {
        #pragma unroll
        for (int it = 0; it < 16; ++it) {
            int idx = tid + it * 256;
            int m = idx >> 5, c4 = (idx & 31) * 4;
            *reinterpret_cast<float4*>(g_agg + (size_t)(row0 + m) * DIM + c4) =
                make_float4(0.f, 0.f, 0.f, 0.f);
        }
    }
    float c[8][8];
    #pragma unroll
    for (int i = 0; i < 8; ++i)
        #pragma unroll
        for (int j = 0; j < 8; ++j) c[i][j] = 0.f;
    mma128(sA, sW, c, m0, n0);
    __syncthreads();   // everyone done reading sA before overwrite

    // x1 = ssp(c + cf2b) into sA; load int weights
    {
        float bb[8];
        #pragma unroll
        for (int j = 0; j < 8; ++j) bb[j] = __ldg(cf2b + n0 + j);
        #pragma unroll
        for (int i = 0; i < 8; ++i)
            #pragma unroll
            for (int j = 0; j < 8; ++j)
                sA[(m0 + i) * 132 + n0 + j] = sspf(c[i][j] + bb[j]);
    }
    #pragma unroll
    for (int it = 0; it < 16; ++it) {
        int idx = tid + it * 256;
        *reinterpret_cast<float4*>(sW + idx * 4) =
            *reinterpret_cast<const float4*>(intW + (size_t)idx * 4);
    }
    __syncthreads();
    #pragma unroll
    for (int i = 0; i < 8; ++i)
        #pragma unroll
        for (int j = 0; j < 8; ++j) c[i][j] = 0.f;
    mma128(sA, sW, c, m0, n0);
    __syncthreads();

    // hnew = h + c + intb -> global (+ stage into sA if next GEMM)
    {
        float bb[8];
        #pragma unroll
        for (int j = 0; j < 8; ++j) bb[j] = __ldg(intb + n0 + j);
        #pragma unroll
        for (int i = 0; i < 8; ++i) {
            size_t off = (size_t)(row0 + m0 + i) * DIM + n0;
            float4 h0 = *reinterpret_cast<const float4*>(g_h + off);
            float4 h1 = *reinterpret_cast<const float4*>(g_h + off + 4);
            h0.x += c[i][0] + bb[0];
            h0.y += c[i][1] + bb[1];
            h0.z += c[i][2] + bb[2];
            h0.w += c[i][3] + bb[3];
            h1.x += c[i][4] + bb[4];
            h1.y += c[i][5] + bb[5];
            h1.z += c[i][6] + bb[6];
            h1.w += c[i][7] + bb[7];
            *reinterpret_cast<float4*>(g_h + off)     = h0;
            *reinterpret_cast<float4*>(g_h + off + 4) = h1;
            if (hasNext) {
                float* p = sA + (m0 + i) * 132 + n0;
                *reinterpret_cast<float4*>(p)     = h0;
                *reinterpret_cast<float4*>(p + 4) = h1;
            }
        }
    }
    if (!hasNext) return;

    #pragma unroll
    for (int it = 0; it < 16; ++it) {
        int idx = tid + it * 256;
        *reinterpret_cast<float4*>(sW + idx * 4) =
            *reinterpret_cast<const float4*>(cf1Wn + (size_t)idx * 4);
    }
    __syncthreads();
    #pragma unroll
    for (int i = 0; i < 8; ++i)
        #pragma unroll
        for (int j = 0; j < 8; ++j) c[i][j] = 0.f;
    mma128(sA, sW, c, m0, n0);
    #pragma unroll
    for (int i = 0; i < 8; ++i) {
        size_t off = (size_t)(row0 + m0 + i) * DIM + n0;
        *reinterpret_cast<float4*>(g_xh + off)     = make_float4(c[i][0], c[i][1], c[i][2], c[i][3]);
        *reinterpret_cast<float4*>(g_xh + off + 4) = make_float4(c[i][4], c[i][5], c[i][6], c[i][7]);
    }
}

// -------------------- readout: ssp(h@lin1+b)@lin2+b, segment-sum by batch --
__global__ void k_readout(const int* __restrict__ batch,
                          const float* __restrict__ l1W, const float* __restrict__ l1b,
                          const float* __restrict__ l2W, const float* __restrict__ l2b,
                          float* __restrict__ out) {
    __shared__ float sW1[DIM * 64];
    __shared__ float sW2[64];
    __shared__ float sh[8 * DIM];
    int tid = threadIdx.x, lane = tid & 31, wid = tid >> 5;
    for (int i = tid; i < DIM * 64; i += 256) sW1[i] = l1W[i];
    if (tid < 64) sW2[tid] = l2W[tid];
    int n = blockIdx.x * 8 + wid;
    float4 hv = reinterpret_cast<const float4*>(g_h + (size_t)n * DIM)[lane];
    *reinterpret_cast<float4*>(sh + wid * DIM + lane * 4) = hv;
    __syncthreads();
    float t0 = __ldg(l1b + lane), t1 = __ldg(l1b + lane + 32);
    const float* hr = sh + wid * DIM;
    #pragma unroll 8
    for (int j = 0; j < DIM; ++j) {
        float hj = hr[j];
        t0 = fmaf(hj, sW1[j * 64 + lane], t0);
        t1 = fmaf(hj, sW1[j * 64 + lane + 32], t1);
    }
    float y = sspf(t0) * sW2[lane] + sspf(t1) * sW2[lane + 32];
    #pragma unroll
    for (int o = 16; o; o >>= 1) y += __shfl_xor_sync(0xffffffffu, y, o);
    if (lane == 0) atomicAdd(out + __ldg(batch + n), y + __ldg(l2b));
}

// -------------------- launch -----------------------------------------------
extern "C" void kernel_launch(void* const* d_in, const int* in_sizes, int n_in,
                              void* d_out, int out_size) {
    const float* z    = (const float*)d_in[0];
    const float* pos  = (const float*)d_in[1];
    const int*   batc = (const int*)  d_in[2];
    const int*   esrc = (const int*)  d_in[3];
    const int*   edst = (const int*)  d_in[4];
    const float* embW = (const float*)d_in[5];
    const float* embB = (const float*)d_in[6];
    const float* W1   = (const float*)d_in[7];
    const float* b1   = (const float*)d_in[8];
    const float* W2   = (const float*)d_in[9];
    const float* b2   = (const float*)d_in[10];
    const float* cf1  = (const float*)d_in[11];
    const float* cf2  = (const float*)d_in[12];
    const float* cf2b = (const float*)d_in[13];
    const float* ilW  = (const float*)d_in[14];
    const float* ilb  = (const float*)d_in[15];
    const float* l1W  = (const float*)d_in[16];
    const float* l1b  = (const float*)d_in[17];
    const float* l2W  = (const float*)d_in[18];
    const float* l2b  = (const float*)d_in[19];
    float* out = (float*)d_out;

    int smemNode = (128 * 132 + 128 * 128) * 4;              // 133120 B
    int smemTbl  = (128 * 132 + 128 * 128 + 128 * 52) * 4;   // 159744 B
    cudaFuncSetAttribute(k_node,  cudaFuncAttributeMaxDynamicSharedMemorySize, smemNode);
    cudaFuncSetAttribute(k_table, cudaFuncAttributeMaxDynamicSharedMemorySize, smemTbl);

    k_prep<<<1, DIM>>>(embW, embB, cf1);
    k_embed<<<(NATOMS * DIM / 4) / 256, 256>>>(z, embW, embB, out);
    k_dist<<<NEDGES / 256, 256>>>(pos, esrc, edst);
    k_table<<<LINT * (TBL / 128), 256, smemTbl>>>(W1, b1, W2, b2);

    for (int l = 0; l < LINT; ++l) {
        k_edge<<<NEDGES / 8, 256>>>(esrc, edst, l);
        const float* cf1n = (l + 1 < LINT) ? (cf1 + (size_t)(l + 1) * DIM * DIM) : cf1;
        k_node<<<NATOMS / 128, 256, smemNode>>>(
            cf2 + (size_t)l * DIM * DIM, cf2b + l * DIM,
            ilW + (size_t)l * DIM * DIM, ilb + l * DIM,
            cf1n, (l + 1 < LINT) ? 1 : 0);
    }
    k_readout<<<NATOMS / 8, 256>>>(batc, l1W, l1b, l2W, l2b, out);
}

// round 17
// speedup vs baseline: 1.0446x; 1.0410x over previous
#include <cuda_runtime.h>
#include <math.h>
#include <stdint.h>

#define NATOMS 16384
#define NEDGES 262144
#define DIM    128
#define GDIM   50
#define LINT   4
#define TBL    4096
#define NMOLS  32

#define DMAXF  1.74f
#define LOG2C  0.69314718055994530942f
#define PIC    3.14159265358979323846f

// -------------------- scratch (static device globals; no runtime alloc) ----
__device__ __align__(16) float g_h[NATOMS * DIM];
__device__ __align__(16) float g_xh[NATOMS * DIM];
__device__ __align__(16) float g_agg[NATOMS * DIM];
__device__ __align__(16) float g_dist[NEDGES];
__device__ __align__(16) float g_table[(size_t)LINT * TBL * DIM];
__device__ __align__(16) float g_u[DIM];
__device__ __align__(16) float g_v[DIM];

__device__ __forceinline__ float sspf(float x) {
    return fmaxf(x, 0.0f) + log1pf(expf(-fabsf(x))) - LOG2C;
}

// -------- swizzled transposed-A addressing: SA[k][m], quad ^= (k>>2)&31 ----
__device__ __forceinline__ int sa_off(int k, int m) {
    return k * DIM + (((((m >> 2) ^ (k >> 2)) & 31) << 2) | (m & 3));
}

// -------------------- prep: u = emb_W@cf1[0], v = emb_b@cf1[0] -------------
__global__ void k_prep(const float* __restrict__ eW, const float* __restrict__ eb,
                       const float* __restrict__ cf1) {
    int f = threadIdx.x;
    float u = 0.f, v = 0.f;
    #pragma unroll 8
    for (int d = 0; d < DIM; ++d) {
        float w = __ldg(cf1 + d * DIM + f);
        u = fmaf(__ldg(eW + d), w, u);
        v = fmaf(__ldg(eb + d), w, v);
    }
    g_u[f] = u;
    g_v[f] = v;
}

// -------------------- embed: h = z*W+b; xh = z*u+v; zero agg + out ---------
__global__ void k_embed(const float* __restrict__ z,
                        const float* __restrict__ eW,
                        const float* __restrict__ eb,
                        float* __restrict__ out) {
    int idx = blockIdx.x * blockDim.x + threadIdx.x;   // float4 index
    if (blockIdx.x == 0 && threadIdx.x < NMOLS) out[threadIdx.x] = 0.0f;
    int n = idx >> 5;
    int c = (idx & 31) << 2;
    float zv = __ldg(z + n);
    float4 w = *reinterpret_cast<const float4*>(eW + c);
    float4 b = *reinterpret_cast<const float4*>(eb + c);
    float4 h;
    h.x = fmaf(zv, w.x, b.x); h.y = fmaf(zv, w.y, b.y);
    h.z = fmaf(zv, w.z, b.z); h.w = fmaf(zv, w.w, b.w);
    size_t off = (size_t)n * DIM + c;
    *reinterpret_cast<float4*>(g_h + off) = h;
    float4 u = *reinterpret_cast<const float4*>(g_u + c);
    float4 v = *reinterpret_cast<const float4*>(g_v + c);
    float4 x;
    x.x = fmaf(zv, u.x, v.x); x.y = fmaf(zv, u.y, v.y);
    x.z = fmaf(zv, u.z, v.z); x.w = fmaf(zv, u.w, v.w);
    *reinterpret_cast<float4*>(g_xh + off) = x;
    *reinterpret_cast<float4*>(g_agg + off) = make_float4(0.f, 0.f, 0.f, 0.f);
}

// -------------------- edge distances ---------------------------------------
__global__ void k_dist(const float* __restrict__ pos,
                       const int* __restrict__ src,
                       const int* __restrict__ dst) {
    int e = blockIdx.x * blockDim.x + threadIdx.x;
    int s = __ldg(src + e);
    int d = __ldg(dst + e);
    float dx = __ldg(pos + s * 3 + 0) - __ldg(pos + d * 3 + 0);
    float dy = __ldg(pos + s * 3 + 1) - __ldg(pos + d * 3 + 1);
    float dz = __ldg(pos + s * 3 + 2) - __ldg(pos + d * 3 + 2);
    g_dist[e] = sqrtf(fmaf(dx, dx, fmaf(dy, dy, fmaf(dz, dz, 1e-12f))));
}

// -------------------- transposed-A / permuted-B GEMM micro-kernel ----------
// sA: [K][128] k-major, quad-swizzled. sW: [K][128] with quads perfect-shuffled
// (orig quad q at position (q>>1)|((q&1)<<4)). c[8][8] over (m0..m0+7, n0..n0+7).
template<int K>
__device__ __forceinline__ void mmaT(const float* __restrict__ sA,
                                     const float* __restrict__ sW,
                                     float c[8][8], int m0, int n0) {
    const int e0 = m0 >> 2;        // even
    const int nh = n0 >> 1;        // B quad offsets nh, nh+64
    #pragma unroll 2
    for (int k = 0; k < K; ++k) {
        int q0 = (((e0 ^ (k >> 2)) & 31) << 2);
        const float* ar = sA + k * DIM;
        float4 a0 = *reinterpret_cast<const float4*>(ar + q0);
        float4 a1 = *reinterpret_cast<const float4*>(ar + (q0 ^ 4));
        const float* br = sW + k * DIM + nh;
        float4 b0 = *reinterpret_cast<const float4*>(br);
        float4 b1 = *reinterpret_cast<const float4*>(br + 64);
        float aa[8] = {a0.x, a0.y, a0.z, a0.w, a1.x, a1.y, a1.z, a1.w};
        float bb[8] = {b0.x, b0.y, b0.z, b0.w, b1.x, b1.y, b1.z, b1.w};
        #pragma unroll
        for (int i = 0; i < 8; ++i)
            #pragma unroll
            for (int j = 0; j < 8; ++j)
                c[i][j] = fmaf(aa[i], bb[j], c[i][j]);
    }
}

__device__ __forceinline__ void zero88(float c[8][8]) {
    #pragma unroll
    for (int i = 0; i < 8; ++i)
        #pragma unroll
        for (int j = 0; j < 8; ++j) c[i][j] = 0.f;
}

// stage weight [128][128] row-major global -> perm-shuffled smem (256 thr)
__device__ __forceinline__ void stage_w(float* __restrict__ sW,
                                        const float* __restrict__ W, int tid) {
    #pragma unroll
    for (int it = 0; it < 16; ++it) {
        int idx = tid + it * 256;          // quad index 0..4095
        int k = idx >> 5, q = idx & 31;
        int P = (q >> 1) | ((q & 1) << 4);
        *reinterpret_cast<float4*>(sW + k * DIM + (P << 2)) =
            *reinterpret_cast<const float4*>(W + (size_t)idx * 4);
    }
}

// write thread's 8x8 register tile into transposed sA (rows = n-dim)
__device__ __forceinline__ void store_tileT(float* __restrict__ sA,
                                            const float c[8][8],
                                            int m0, int n0) {
    const int e0 = m0 >> 2;
    #pragma unroll
    for (int j = 0; j < 8; ++j) {
        int r = n0 + j;
        int q0 = (((e0 ^ (r >> 2)) & 31) << 2);
        *reinterpret_cast<float4*>(sA + r * DIM + q0) =
            make_float4(c[0][j], c[1][j], c[2][j], c[3][j]);
        *reinterpret_cast<float4*>(sA + r * DIM + (q0 ^ 4)) =
            make_float4(c[4][j], c[5][j], c[6][j], c[7][j]);
    }
}

// -------------------- table build as two chained GEMMs ---------------------
// out[l,t,f] = (ssp(rbf[t,:]@W1[l] + b1[l]) @ W2[l] + b2[l]) * C(t)
__global__ void __launch_bounds__(256, 1) k_table(
    const float* __restrict__ W1, const float* __restrict__ b1,
    const float* __restrict__ W2, const float* __restrict__ b2) {
    extern __shared__ float sm[];
    float* sX = sm;                  // [128][128] transposed x1
    float* sW = sm + DIM * DIM;      // weights (perm-shuffled)
    float* sR = sW + DIM * DIM;      // [50][128] transposed rbf
    int tid = threadIdx.x;
    int l   = blockIdx.x >> 5;
    int t0  = (blockIdx.x & 31) * 128;
    const float dstep = DMAXF / (float)(TBL - 1);

    // stage W1 [50][128] perm-shuffled
    for (int idx = tid; idx < GDIM * 32; idx += 256) {
        int k = idx >> 5, q = idx & 31;
        int P = (q >> 1) | ((q & 1) << 4);
        *reinterpret_cast<float4*>(sW + k * DIM + (P << 2)) =
            *reinterpret_cast<const float4*>(W1 + (size_t)l * GDIM * DIM + idx * 4);
    }
    // rbf transposed [g][m]
    for (int idx = tid; idx < GDIM * 128; idx += 256) {
        int g = idx >> 7, m = idx & 127;
        float d = (float)(t0 + m) * dstep;
        float u = d - (float)g * (5.0f / 49.0f);
        sR[sa_off(g, m)] = expf(-4.0f * u * u);
    }
    __syncthreads();

    int m0 = (tid >> 4) * 8, n0 = (tid & 15) * 8;
    float c[8][8];
    zero88(c);
    mmaT<GDIM>(sR, sW, c, m0, n0);
    __syncthreads();

    // x1 = ssp(c + b1) -> sX (transposed); stage W2
    {
        float bb[8], t[8][8];
        #pragma unroll
        for (int j = 0; j < 8; ++j) bb[j] = __ldg(b1 + l * DIM + n0 + j);
        #pragma unroll
        for (int i = 0; i < 8; ++i)
            #pragma unroll
            for (int j = 0; j < 8; ++j) t[i][j] = sspf(c[i][j] + bb[j]);
        store_tileT(sX, t, m0, n0);
    }
    stage_w(sW, W2 + (size_t)l * DIM * DIM, tid);
    __syncthreads();

    zero88(c);
    mmaT<DIM>(sX, sW, c, m0, n0);

    // store: (c + b2) * C(d)
    {
        float bb[8];
        #pragma unroll
        for (int j = 0; j < 8; ++j) bb[j] = __ldg(b2 + l * DIM + n0 + j);
        #pragma unroll
        for (int i = 0; i < 8; ++i) {
            int row = m0 + i;
            float d = (float)(t0 + row) * dstep;
            float C = 0.5f * (cosf(d * (PIC / 5.0f)) + 1.0f);
            size_t off = ((size_t)l * TBL + t0 + row) * DIM + n0;
            *reinterpret_cast<float4*>(g_table + off) = make_float4(
                (c[i][0] + bb[0]) * C, (c[i][1] + bb[1]) * C,
                (c[i][2] + bb[2]) * C, (c[i][3] + bb[3]) * C);
            *reinterpret_cast<float4*>(g_table + off + 4) = make_float4(
                (c[i][4] + bb[4]) * C, (c[i][5] + bb[5]) * C,
                (c[i][6] + bb[6]) * C, (c[i][7] + bb[7]) * C);
        }
    }
}

// -------------------- edge pass: gather * lerp(table) -> scatter-add -------
__global__ void k_edge(const int* __restrict__ src, const int* __restrict__ dst, int l) {
    int gt   = blockIdx.x * 256 + threadIdx.x;
    int e    = gt >> 5;
    int lane = gt & 31;
    int s  = __ldg(src + e);
    int dd = __ldg(dst + e);
    float dist = g_dist[e];
    float p = dist * ((float)(TBL - 1) / DMAXF);
    int   i = (int)p;
    i = min(i, TBL - 2);
    float w = p - (float)i;
    const float4* trow = reinterpret_cast<const float4*>(g_table + ((size_t)l * TBL + i) * DIM) + lane;
    float4 a = trow[0];
    float4 b = trow[32];
    float4 xj = reinterpret_cast<const float4*>(g_xh + (size_t)s * DIM)[lane];
    float4 v;
    v.x = xj.x * fmaf(w, b.x - a.x, a.x);
    v.y = xj.y * fmaf(w, b.y - a.y, a.y);
    v.z = xj.z * fmaf(w, b.z - a.z, a.z);
    v.w = xj.w * fmaf(w, b.w - a.w, a.w);
    float* outp = g_agg + (size_t)dd * DIM + lane * 4;
    asm volatile("red.global.add.v4.f32 [%0], {%1,%2,%3,%4};"
                 :: "l"(outp), "f"(v.x), "f"(v.y), "f"(v.z), "f"(v.w) : "memory");
}

// -------------------- fused node update: 3 chained GEMMs per tile ----------
// x1 = ssp(agg@cf2 + b); x2 = x1@int + b; h += x2; xh = h@cf1_next (if any).
// Also zeroes its g_agg tile for the next layer's scatter.
__global__ void __launch_bounds__(256, 1) k_node(
    const float* __restrict__ cf2W, const float* __restrict__ cf2b,
    const float* __restrict__ intW, const float* __restrict__ intb,
    const float* __restrict__ cf1Wn, int hasNext) {
    extern __shared__ float sm[];
    float* sA = sm;                 // [128][128] transposed A
    float* sW = sm + DIM * DIM;     // [128][128] perm-shuffled weights
    int tid  = threadIdx.x;
    int row0 = blockIdx.x * 128;
    int m0 = (tid >> 4) * 8, n0 = (tid & 15) * 8;

    // stage A = agg tile (transposed+swizzled); W = cf2 (perm)
    #pragma unroll
    for (int it = 0; it < 16; ++it) {
        int idx = tid + it * 256;
        int m = idx & 127;
        int kb = (idx >> 7) << 2;                  // 0,4,...,124
        float4 v = *reinterpret_cast<const float4*>(g_agg + (size_t)(row0 + m) * DIM + kb);
        int base = (((((m >> 2) ^ (kb >> 2)) & 31) << 2) | (m & 3));
        sA[(kb + 0) * DIM + base] = v.x;
        sA[(kb + 1) * DIM + base] = v.y;
        sA[(kb + 2) * DIM + base] = v.z;
        sA[(kb + 3) * DIM + base] = v.w;
    }
    stage_w(sW, cf2W, tid);
    __syncthreads();
    // zero our agg tile for the next layer (overlaps with MMA below)
    if (hasNext) {
        #pragma unroll
        for (int it = 0; it < 16; ++it) {
            int idx = tid + it * 256;
            int m = idx >> 5, c4 = (idx & 31) * 4;
            *reinterpret_cast<float4*>(g_agg + (size_t)(row0 + m) * DIM + c4) =
                make_float4(0.f, 0.f, 0.f, 0.f);
        }
    }
    float c[8][8];
    zero88(c);
    mmaT<DIM>(sA, sW, c, m0, n0);
    __syncthreads();   // everyone done reading sA before overwrite

    // x1 = ssp(c + cf2b) into sA (transposed); load int weights
    {
        float bb[8], t[8][8];
        #pragma unroll
        for (int j = 0; j < 8; ++j) bb[j] = __ldg(cf2b + n0 + j);
        #pragma unroll
        for (int i = 0; i < 8; ++i)
            #pragma unroll
            for (int j = 0; j < 8; ++j) t[i][j] = sspf(c[i][j] + bb[j]);
        store_tileT(sA, t, m0, n0);
    }
    stage_w(sW, intW, tid);
    __syncthreads();
    zero88(c);
    mmaT<DIM>(sA, sW, c, m0, n0);
    __syncthreads();

    // hnew = h + c + intb -> global (+ stage into sA if next GEMM)
    {
        float bb[8], t[8][8];
        #pragma unroll
        for (int j = 0; j < 8; ++j) bb[j] = __ldg(intb + n0 + j);
        #pragma unroll
        for (int i = 0; i < 8; ++i) {
            size_t off = (size_t)(row0 + m0 + i) * DIM + n0;
            float4 h0 = *reinterpret_cast<const float4*>(g_h + off);
            float4 h1 = *reinterpret_cast<const float4*>(g_h + off + 4);
            h0.x += c[i][0] + bb[0];
            h0.y += c[i][1] + bb[1];
            h0.z += c[i][2] + bb[2];
            h0.w += c[i][3] + bb[3];
            h1.x += c[i][4] + bb[4];
            h1.y += c[i][5] + bb[5];
            h1.z += c[i][6] + bb[6];
            h1.w += c[i][7] + bb[7];
            *reinterpret_cast<float4*>(g_h + off)     = h0;
            *reinterpret_cast<float4*>(g_h + off + 4) = h1;
            t[i][0] = h0.x; t[i][1] = h0.y; t[i][2] = h0.z; t[i][3] = h0.w;
            t[i][4] = h1.x; t[i][5] = h1.y; t[i][6] = h1.z; t[i][7] = h1.w;
        }
        if (hasNext) store_tileT(sA, t, m0, n0);
    }
    if (!hasNext) return;

    stage_w(sW, cf1Wn, tid);
    __syncthreads();
    zero88(c);
    mmaT<DIM>(sA, sW, c, m0, n0);
    #pragma unroll
    for (int i = 0; i < 8; ++i) {
        size_t off = (size_t)(row0 + m0 + i) * DIM + n0;
        *reinterpret_cast<float4*>(g_xh + off)     = make_float4(c[i][0], c[i][1], c[i][2], c[i][3]);
        *reinterpret_cast<float4*>(g_xh + off + 4) = make_float4(c[i][4], c[i][5], c[i][6], c[i][7]);
    }
}

// -------------------- readout: ssp(h@lin1+b)@lin2+b, segment-sum by batch --
__global__ void k_readout(const int* __restrict__ batch,
                          const float* __restrict__ l1W, const float* __restrict__ l1b,
                          const float* __restrict__ l2W, const float* __restrict__ l2b,
                          float* __restrict__ out) {
    __shared__ float sW1[DIM * 64];
    __shared__ float sW2[64];
    __shared__ float sh[8 * DIM];
    int tid = threadIdx.x, lane = tid & 31, wid = tid >> 5;
    for (int i = tid; i < DIM * 64; i += 256) sW1[i] = l1W[i];
    if (tid < 64) sW2[tid] = l2W[tid];
    int n = blockIdx.x * 8 + wid;
    float4 hv = reinterpret_cast<const float4*>(g_h + (size_t)n * DIM)[lane];
    *reinterpret_cast<float4*>(sh + wid * DIM + lane * 4) = hv;
    __syncthreads();
    float t0 = __ldg(l1b + lane), t1 = __ldg(l1b + lane + 32);
    const float* hr = sh + wid * DIM;
    #pragma unroll 8
    for (int j = 0; j < DIM; ++j) {
        float hj = hr[j];
        t0 = fmaf(hj, sW1[j * 64 + lane], t0);
        t1 = fmaf(hj, sW1[j * 64 + lane + 32], t1);
    }
    float y = sspf(t0) * sW2[lane] + sspf(t1) * sW2[lane + 32];
    #pragma unroll
    for (int o = 16; o; o >>= 1) y += __shfl_xor_sync(0xffffffffu, y, o);
    if (lane == 0) atomicAdd(out + __ldg(batch + n), y + __ldg(l2b));
}

// -------------------- launch -----------------------------------------------
extern "C" void kernel_launch(void* const* d_in, const int* in_sizes, int n_in,
                              void* d_out, int out_size) {
    const float* z    = (const float*)d_in[0];
    const float* pos  = (const float*)d_in[1];
    const int*   batc = (const int*)  d_in[2];
    const int*   esrc = (const int*)  d_in[3];
    const int*   edst = (const int*)  d_in[4];
    const float* embW = (const float*)d_in[5];
    const float* embB = (const float*)d_in[6];
    const float* W1   = (const float*)d_in[7];
    const float* b1   = (const float*)d_in[8];
    const float* W2   = (const float*)d_in[9];
    const float* b2   = (const float*)d_in[10];
    const float* cf1  = (const float*)d_in[11];
    const float* cf2  = (const float*)d_in[12];
    const float* cf2b = (const float*)d_in[13];
    const float* ilW  = (const float*)d_in[14];
    const float* ilb  = (const float*)d_in[15];
    const float* l1W  = (const float*)d_in[16];
    const float* l1b  = (const float*)d_in[17];
    const float* l2W  = (const float*)d_in[18];
    const float* l2b  = (const float*)d_in[19];
    float* out = (float*)d_out;

    int smemNode = (DIM * DIM * 2) * 4;                        // 131072 B
    int smemTbl  = (DIM * DIM * 2 + GDIM * DIM) * 4;           // 156672 B
    cudaFuncSetAttribute(k_node,  cudaFuncAttributeMaxDynamicSharedMemorySize, smemNode);
    cudaFuncSetAttribute(k_table, cudaFuncAttributeMaxDynamicSharedMemorySize, smemTbl);

    k_prep<<<1, DIM>>>(embW, embB, cf1);
    k_embed<<<(NATOMS * DIM / 4) / 256, 256>>>(z, embW, embB, out);
    k_dist<<<NEDGES / 256, 256>>>(pos, esrc, edst);
    k_table<<<LINT * (TBL / 128), 256, smemTbl>>>(W1, b1, W2, b2);

    for (int l = 0; l < LINT; ++l) {
        k_edge<<<NEDGES / 8, 256>>>(esrc, edst, l);
        const float* cf1n = (l + 1 < LINT) ? (cf1 + (size_t)(l + 1) * DIM * DIM) : cf1;
        k_node<<<NATOMS / 128, 256, smemNode>>>(
            cf2 + (size_t)l * DIM * DIM, cf2b + l * DIM,
            ilW + (size_t)l * DIM * DIM, ilb + l * DIM,
            cf1n, (l + 1 < LINT) ? 1 : 0);
    }
    k_readout<<<NATOMS / 8, 256>>>(batc, l1W, l1b, l2W, l2b, out);
}